// round 1
// baseline (speedup 1.0000x reference)
#include <cuda_runtime.h>
#include <cuda_bf16.h>

#define TOK 49
#define HDIM 32
#define NH 8
#define NWIN 4096
#define MTOT (NWIN * TOK)   /* 200704 */
#define KDIM 256
#define NMASK 64

// ---------------- scratch (device globals: allocation-free) ----------------
__device__ float g_q[NWIN * NH * TOK * HDIM];   // [b,h,t,d]
__device__ float g_k[NWIN * NH * TOK * HDIM];
__device__ float g_v[NWIN * NH * TOK * HDIM];
__device__ float g_att[MTOT * KDIM];            // [b*49+t, h*32+d]

__device__ __forceinline__ float4 ld4(const float* p) {
    return *reinterpret_cast<const float4*>(p);
}
__device__ __forceinline__ void st4(float* p, float4 v) {
    *reinterpret_cast<float4*>(p) = v;
}

// ---------------------------------------------------------------------------
// SGEMM (NT): C[m,n] = sum_k A[m,k] * B[n,k] + bias[n]
// BM=BN=128, BK=8, 256 threads, 8x8 register tile per thread.
// MODE 0: A = x, N = 768, epilogue scatters into g_q/g_k/g_v ([b,h,t,d]),
//         q scaled by HDIM^-0.5.
// MODE 1: A = g_att (internal), plain epilogue into C.
// ---------------------------------------------------------------------------
template <int MODE>
__global__ __launch_bounds__(256, 2)
void sgemm_nt(const float* __restrict__ Ain, const float* __restrict__ B,
              const float* __restrict__ bias, float* __restrict__ C, int N)
{
    const int K = KDIM;
    const float* A = (MODE == 1) ? (const float*)g_att : Ain;

    __shared__ float As[8][128];
    __shared__ float Bs[8][128];

    const int tid  = threadIdx.x;
    const int m0   = blockIdx.x * 128;
    const int n0   = blockIdx.y * 128;
    const int lrow = tid >> 1;          // 0..127
    const int lk   = (tid & 1) * 4;     // 0 or 4

    const float* Ag = A + (m0 + lrow) * K + lk;
    const float* Bg = B + (n0 + lrow) * K + lk;

    const int ty = tid >> 4;            // 0..15
    const int tx = tid & 15;            // 0..15

    float acc[8][8];
#pragma unroll
    for (int i = 0; i < 8; i++)
#pragma unroll
        for (int j = 0; j < 8; j++) acc[i][j] = 0.f;

    for (int kt = 0; kt < K; kt += 8) {
        float4 av = ld4(Ag + kt);
        float4 bv = ld4(Bg + kt);
        __syncthreads();
        As[lk + 0][lrow] = av.x;
        As[lk + 1][lrow] = av.y;
        As[lk + 2][lrow] = av.z;
        As[lk + 3][lrow] = av.w;
        Bs[lk + 0][lrow] = bv.x;
        Bs[lk + 1][lrow] = bv.y;
        Bs[lk + 2][lrow] = bv.z;
        Bs[lk + 3][lrow] = bv.w;
        __syncthreads();
#pragma unroll
        for (int kk = 0; kk < 8; kk++) {
            float a[8], b[8];
            *reinterpret_cast<float4*>(a)     = ld4(&As[kk][ty * 8]);
            *reinterpret_cast<float4*>(a + 4) = ld4(&As[kk][ty * 8 + 4]);
            *reinterpret_cast<float4*>(b)     = ld4(&Bs[kk][tx * 8]);
            *reinterpret_cast<float4*>(b + 4) = ld4(&Bs[kk][tx * 8 + 4]);
#pragma unroll
            for (int i = 0; i < 8; i++)
#pragma unroll
                for (int j = 0; j < 8; j++) acc[i][j] = fmaf(a[i], b[j], acc[i][j]);
        }
    }

    if (MODE == 0) {
        const float SC = 0.17677669529663687f;  // 32^-0.5
#pragma unroll
        for (int i = 0; i < 8; i++) {
            const int m  = m0 + ty * 8 + i;
            const int bw = m / TOK;
            const int t  = m - bw * TOK;
#pragma unroll
            for (int j4 = 0; j4 < 2; j4++) {
                const int n     = n0 + tx * 8 + j4 * 4;
                const int which = n >> 8;
                const int h     = (n >> 5) & 7;
                const int d     = n & 31;
                float4 v;
                v.x = acc[i][j4 * 4 + 0] + bias[n + 0];
                v.y = acc[i][j4 * 4 + 1] + bias[n + 1];
                v.z = acc[i][j4 * 4 + 2] + bias[n + 2];
                v.w = acc[i][j4 * 4 + 3] + bias[n + 3];
                if (which == 0) { v.x *= SC; v.y *= SC; v.z *= SC; v.w *= SC; }
                float* dst = (which == 0) ? g_q : (which == 1) ? g_k : g_v;
                st4(&dst[((bw * NH + h) * TOK + t) * HDIM + d], v);
            }
        }
    } else {
#pragma unroll
        for (int i = 0; i < 8; i++) {
            const int m = m0 + ty * 8 + i;
            float* cp = C + m * N + n0 + tx * 8;
#pragma unroll
            for (int j4 = 0; j4 < 2; j4++) {
                const int n = n0 + tx * 8 + j4 * 4;
                float4 v;
                v.x = acc[i][j4 * 4 + 0] + bias[n + 0];
                v.y = acc[i][j4 * 4 + 1] + bias[n + 1];
                v.z = acc[i][j4 * 4 + 2] + bias[n + 2];
                v.w = acc[i][j4 * 4 + 3] + bias[n + 3];
                st4(cp + j4 * 4, v);
            }
        }
    }
}

// ---------------------------------------------------------------------------
// Attention: one block per (window b, head h). 256 threads.
// S = q k^T (+bias+mask), row softmax, O = P @ v -> g_att[b*49+t, h*32+d]
// ---------------------------------------------------------------------------
__global__ __launch_bounds__(256, 3)
void attn_kernel(const float* __restrict__ bias_table,
                 const int* __restrict__ rel_index,
                 const float* __restrict__ mask)
{
    __shared__ float sq[56][32];
    __shared__ float sk[56][32];
    __shared__ float sv[56][32];
    __shared__ float S[56][56];

    const int tid = threadIdx.x;
    const int bh  = blockIdx.x;
    const int b   = bh >> 3;
    const int h   = bh & 7;
    const int base = bh * (TOK * HDIM);   // 1568 floats per (b,h)

    // load q,k,v tiles (zero-pad rows 49..55)
    for (int i = tid; i < 56 * 8; i += 256) {
        const int r = i >> 3;
        const int c = (i & 7) * 4;
        float4 vq, vk, vv;
        if (r < TOK) {
            vq = ld4(g_q + base + r * HDIM + c);
            vk = ld4(g_k + base + r * HDIM + c);
            vv = ld4(g_v + base + r * HDIM + c);
        } else {
            vq = make_float4(0.f, 0.f, 0.f, 0.f);
            vk = vq; vv = vq;
        }
        st4(&sq[r][c], vq);
        st4(&sk[r][c], vk);
        st4(&sv[r][c], vv);
    }
    __syncthreads();

    // S = q k^T : 14x14 thread grid, 4x4 per thread
    if (tid < 196) {
        const int ty = tid / 14, tx = tid - ty * 14;
        const int i0 = ty * 4, j0 = tx * 4;
        float acc[4][4];
#pragma unroll
        for (int i = 0; i < 4; i++)
#pragma unroll
            for (int j = 0; j < 4; j++) acc[i][j] = 0.f;
#pragma unroll
        for (int d4 = 0; d4 < 8; d4++) {
            float4 qa[4], kb[4];
#pragma unroll
            for (int ii = 0; ii < 4; ii++) qa[ii] = ld4(&sq[i0 + ii][d4 * 4]);
#pragma unroll
            for (int jj = 0; jj < 4; jj++) kb[jj] = ld4(&sk[j0 + jj][d4 * 4]);
#pragma unroll
            for (int ii = 0; ii < 4; ii++)
#pragma unroll
                for (int jj = 0; jj < 4; jj++) {
                    acc[ii][jj] = fmaf(qa[ii].x, kb[jj].x, acc[ii][jj]);
                    acc[ii][jj] = fmaf(qa[ii].y, kb[jj].y, acc[ii][jj]);
                    acc[ii][jj] = fmaf(qa[ii].z, kb[jj].z, acc[ii][jj]);
                    acc[ii][jj] = fmaf(qa[ii].w, kb[jj].w, acc[ii][jj]);
                }
        }
#pragma unroll
        for (int ii = 0; ii < 4; ii++)
            st4(&S[i0 + ii][j0], make_float4(acc[ii][0], acc[ii][1], acc[ii][2], acc[ii][3]));
    }
    __syncthreads();

    // bias + mask
    const float* mrow = mask + (size_t)(b & (NMASK - 1)) * (TOK * TOK);
    for (int e = tid; e < TOK * TOK; e += 256) {
        const int i = e / TOK;
        const int j = e - i * TOK;
        S[i][j] += bias_table[rel_index[e] * NH + h] + mrow[e];
    }
    __syncthreads();

    // softmax: warp per row
    const int warp = tid >> 5, lane = tid & 31;
    for (int i = warp; i < TOK; i += 8) {
        float x0 = S[i][lane];
        float x1 = (lane + 32 < TOK) ? S[i][lane + 32] : -1e30f;
        float mx = fmaxf(x0, x1);
#pragma unroll
        for (int off = 16; off > 0; off >>= 1)
            mx = fmaxf(mx, __shfl_xor_sync(0xffffffffu, mx, off));
        float e0 = __expf(x0 - mx);
        float e1 = (lane + 32 < TOK) ? __expf(x1 - mx) : 0.f;
        float s = e0 + e1;
#pragma unroll
        for (int off = 16; off > 0; off >>= 1)
            s += __shfl_xor_sync(0xffffffffu, s, off);
        const float inv = 1.f / s;
        S[i][lane] = e0 * inv;
        if (lane + 32 < TOK) S[i][lane + 32] = e1 * inv;
    }
    __syncthreads();

    // O = P @ V : 14x8 thread grid, 4x4 per thread
    if (tid < 112) {
        const int ty = tid >> 3, tx = tid & 7;
        const int i0 = ty * 4, d0 = tx * 4;
        float acc[4][4];
#pragma unroll
        for (int i = 0; i < 4; i++)
#pragma unroll
            for (int j = 0; j < 4; j++) acc[i][j] = 0.f;
        for (int j = 0; j < TOK; j++) {
            const float4 vv = ld4(&sv[j][d0]);
#pragma unroll
            for (int ii = 0; ii < 4; ii++) {
                const float p = S[i0 + ii][j];
                acc[ii][0] = fmaf(p, vv.x, acc[ii][0]);
                acc[ii][1] = fmaf(p, vv.y, acc[ii][1]);
                acc[ii][2] = fmaf(p, vv.z, acc[ii][2]);
                acc[ii][3] = fmaf(p, vv.w, acc[ii][3]);
            }
        }
#pragma unroll
        for (int ii = 0; ii < 4; ii++) {
            const int i = i0 + ii;
            if (i < TOK)
                st4(&g_att[(b * TOK + i) * KDIM + h * HDIM + d0],
                    make_float4(acc[ii][0], acc[ii][1], acc[ii][2], acc[ii][3]));
        }
    }
}

// ---------------------------------------------------------------------------
extern "C" void kernel_launch(void* const* d_in, const int* in_sizes, int n_in,
                              void* d_out, int out_size)
{
    const float* x          = (const float*)d_in[0];
    const float* mask       = (const float*)d_in[1];
    const float* qkv_w      = (const float*)d_in[2];
    const float* qkv_b      = (const float*)d_in[3];
    const float* proj_w     = (const float*)d_in[4];
    const float* proj_b     = (const float*)d_in[5];
    const float* bias_table = (const float*)d_in[6];
    const int*   rel_index  = (const int*)d_in[7];
    float*       out        = (float*)d_out;

    // 1) QKV GEMM + scatter to [b,h,t,d] (q pre-scaled)
    dim3 g1(MTOT / 128, 768 / 128);
    sgemm_nt<0><<<g1, 256>>>(x, qkv_w, qkv_b, nullptr, 768);

    // 2) attention per (window, head)
    attn_kernel<<<NWIN * NH, 256>>>(bias_table, rel_index, mask);

    // 3) proj GEMM -> out
    dim3 g2(MTOT / 128, KDIM / 128);
    sgemm_nt<1><<<g2, 256>>>(nullptr, proj_w, proj_b, out, KDIM);
}

// round 3
// speedup vs baseline: 1.3996x; 1.3996x over previous
#include <cuda_runtime.h>
#include <cuda_bf16.h>
#include <cstdint>

#define TOK 49
#define HDIM 32
#define NH 8
#define NWIN 4096
#define MTOT (NWIN * TOK)   /* 200704 */
#define KDIM 256
#define NMASK 64
#define BMSTRIDE 2404

// ---------------- scratch (device globals: allocation-free) ----------------
__device__ float g_q[NWIN * NH * TOK * HDIM];   // [b,h,t,d]
__device__ float g_k[NWIN * NH * TOK * HDIM];
__device__ float g_v[NWIN * NH * TOK * HDIM];
__device__ float g_att[MTOT * KDIM];            // [b*49+t, h*32+d]
__device__ float g_bm[NMASK * NH * BMSTRIDE];   // fused bias+mask per (w,h)

__device__ __forceinline__ float4 ld4(const float* p) {
    return *reinterpret_cast<const float4*>(p);
}
__device__ __forceinline__ void st4(float* p, float4 v) {
    *reinterpret_cast<float4*>(p) = v;
}
__device__ __forceinline__ void st2(float* p, float2 v) {
    *reinterpret_cast<float2*>(p) = v;
}
__device__ __forceinline__ uint32_t f2tf(float f) {
    uint32_t u;
    asm("cvt.rna.tf32.f32 %0, %1;" : "=r"(u) : "f"(f));
    return u;
}
__device__ __forceinline__ void mma_tf32(float c[4],
                                         uint32_t a0, uint32_t a1, uint32_t a2, uint32_t a3,
                                         uint32_t b0, uint32_t b1) {
    asm volatile(
        "mma.sync.aligned.m16n8k8.row.col.f32.tf32.tf32.f32 "
        "{%0,%1,%2,%3}, {%4,%5,%6,%7}, {%8,%9}, {%0,%1,%2,%3};"
        : "+f"(c[0]), "+f"(c[1]), "+f"(c[2]), "+f"(c[3])
        : "r"(a0), "r"(a1), "r"(a2), "r"(a3), "r"(b0), "r"(b1));
}

// ---------------------------------------------------------------------------
// tf32 tensor-core GEMM (NT): C[m,n] = sum_k A[m,k]*B[n,k] + bias[n]
// BM=BN=128, BK=16, 256 threads = 8 warps, warp tile 64x32 (mma m16n8k8).
// MODE 0: A=x, N=768, epilogue scatters into g_q/g_k/g_v, q scaled.
// MODE 1: A=g_att, plain epilogue into C.
// ---------------------------------------------------------------------------
#define SMS 140   // smem row stride (conflict-free fragment loads)

template <int MODE>
__global__ __launch_bounds__(256, 2)
void gemm_tf32(const float* __restrict__ Ain, const float* __restrict__ B,
               const float* __restrict__ bias, float* __restrict__ C, int N)
{
    const int K = KDIM;
    const float* A = (MODE == 1) ? (const float*)g_att : Ain;

    __shared__ uint32_t As[16 * SMS];
    __shared__ uint32_t Bs[16 * SMS];

    const int tid  = threadIdx.x;
    const int m0   = blockIdx.x * 128;
    const int n0   = blockIdx.y * 128;
    const int warp = tid >> 5;
    const int lane = tid & 31;
    const int g    = lane >> 2;       // group id 0..7
    const int tig  = lane & 3;        // thread-in-group 0..3
    const int wm   = warp & 1;        // 0..1
    const int wn   = warp >> 1;       // 0..3
    const int mbase = wm * 64;
    const int nbase = wn * 32;

    // global load mapping: each thread loads 8 consecutive k of one row, per array
    const int r0  = tid >> 1;               // 0..127
    const int kc0 = (tid & 1) * 8;          // 0 or 8

    const float* Ap = A + (size_t)(m0 + r0) * K + kc0;
    const float* Bp = B + (size_t)(n0 + r0) * K + kc0;

    float acc[4][4][4];
#pragma unroll
    for (int mi = 0; mi < 4; mi++)
#pragma unroll
        for (int ni = 0; ni < 4; ni++)
#pragma unroll
            for (int e = 0; e < 4; e++) acc[mi][ni][e] = 0.f;

    float4 pa0 = ld4(Ap), pa1 = ld4(Ap + 4);
    float4 pb0 = ld4(Bp), pb1 = ld4(Bp + 4);

    for (int kt = 0; kt < K; kt += 16) {
        __syncthreads();
        As[(kc0 + 0) * SMS + r0] = f2tf(pa0.x);
        As[(kc0 + 1) * SMS + r0] = f2tf(pa0.y);
        As[(kc0 + 2) * SMS + r0] = f2tf(pa0.z);
        As[(kc0 + 3) * SMS + r0] = f2tf(pa0.w);
        As[(kc0 + 4) * SMS + r0] = f2tf(pa1.x);
        As[(kc0 + 5) * SMS + r0] = f2tf(pa1.y);
        As[(kc0 + 6) * SMS + r0] = f2tf(pa1.z);
        As[(kc0 + 7) * SMS + r0] = f2tf(pa1.w);
        Bs[(kc0 + 0) * SMS + r0] = f2tf(pb0.x);
        Bs[(kc0 + 1) * SMS + r0] = f2tf(pb0.y);
        Bs[(kc0 + 2) * SMS + r0] = f2tf(pb0.z);
        Bs[(kc0 + 3) * SMS + r0] = f2tf(pb0.w);
        Bs[(kc0 + 4) * SMS + r0] = f2tf(pb1.x);
        Bs[(kc0 + 5) * SMS + r0] = f2tf(pb1.y);
        Bs[(kc0 + 6) * SMS + r0] = f2tf(pb1.z);
        Bs[(kc0 + 7) * SMS + r0] = f2tf(pb1.w);
        __syncthreads();

        if (kt + 16 < K) {
            Ap += 16; Bp += 16;
            pa0 = ld4(Ap); pa1 = ld4(Ap + 4);
            pb0 = ld4(Bp); pb1 = ld4(Bp + 4);
        }

#pragma unroll
        for (int k8 = 0; k8 < 16; k8 += 8) {
            // PTX m16n8k8 tf32 fragment layout:
            //   A: a0=(g, tig) a1=(g+8, tig) a2=(g, tig+4) a3=(g+8, tig+4)
            //   B: b0=(tig, g) b1=(tig+4, g)
            const int kr0 = (k8 + tig) * SMS;       // k = tig
            const int kr1 = (k8 + tig + 4) * SMS;   // k = tig + 4
            uint32_t a[4][4], b[4][2];
#pragma unroll
            for (int mi = 0; mi < 4; mi++) {
                const int mg = mbase + mi * 16 + g;
                a[mi][0] = As[kr0 + mg];
                a[mi][1] = As[kr0 + mg + 8];
                a[mi][2] = As[kr1 + mg];
                a[mi][3] = As[kr1 + mg + 8];
            }
#pragma unroll
            for (int ni = 0; ni < 4; ni++) {
                const int ng = nbase + ni * 8 + g;
                b[ni][0] = Bs[kr0 + ng];
                b[ni][1] = Bs[kr1 + ng];
            }
#pragma unroll
            for (int mi = 0; mi < 4; mi++)
#pragma unroll
                for (int ni = 0; ni < 4; ni++)
                    mma_tf32(acc[mi][ni], a[mi][0], a[mi][1], a[mi][2], a[mi][3],
                             b[ni][0], b[ni][1]);
        }
    }

    // epilogue: c0/c1 -> (row g, cols 2*tig..2*tig+1), c2/c3 -> (row g+8)
    if (MODE == 0) {
        const float SC = 0.17677669529663687f;  // 32^-0.5
#pragma unroll
        for (int mi = 0; mi < 4; mi++) {
#pragma unroll
            for (int half = 0; half < 2; half++) {
                const int m  = m0 + mbase + mi * 16 + g + half * 8;
                const int bw = m / TOK;
                const int t  = m - bw * TOK;
#pragma unroll
                for (int ni = 0; ni < 4; ni++) {
                    const int n     = n0 + nbase + ni * 8 + 2 * tig;
                    const int which = n >> 8;
                    const int h     = (n >> 5) & 7;
                    const int d     = n & 31;
                    float2 v;
                    v.x = acc[mi][ni][half * 2 + 0] + bias[n + 0];
                    v.y = acc[mi][ni][half * 2 + 1] + bias[n + 1];
                    if (which == 0) { v.x *= SC; v.y *= SC; }
                    float* dst = (which == 0) ? g_q : (which == 1) ? g_k : g_v;
                    st2(&dst[(size_t)((bw * NH + h) * TOK + t) * HDIM + d], v);
                }
            }
        }
    } else {
#pragma unroll
        for (int mi = 0; mi < 4; mi++) {
#pragma unroll
            for (int half = 0; half < 2; half++) {
                const int m = m0 + mbase + mi * 16 + g + half * 8;
#pragma unroll
                for (int ni = 0; ni < 4; ni++) {
                    const int n = n0 + nbase + ni * 8 + 2 * tig;
                    float2 v;
                    v.x = acc[mi][ni][half * 2 + 0] + bias[n + 0];
                    v.y = acc[mi][ni][half * 2 + 1] + bias[n + 1];
                    st2(C + (size_t)m * N + n, v);
                }
            }
        }
    }
}

// ---------------------------------------------------------------------------
// Precompute fused bias+mask: g_bm[w][h][e] = bias_table[rel_index[e]*8+h] + mask[w][e]
// ---------------------------------------------------------------------------
__global__ void bm_precompute(const float* __restrict__ bias_table,
                              const int* __restrict__ rel_index,
                              const float* __restrict__ mask)
{
    const int w = blockIdx.x >> 3;
    const int h = blockIdx.x & 7;
    float* dst = g_bm + (size_t)blockIdx.x * BMSTRIDE;
    const float* mrow = mask + (size_t)w * (TOK * TOK);
    for (int e = threadIdx.x; e < TOK * TOK; e += 256)
        dst[e] = bias_table[rel_index[e] * NH + h] + mrow[e];
}

// ---------------------------------------------------------------------------
// Attention: one block per (window b, head h). 256 threads.
// ---------------------------------------------------------------------------
__global__ __launch_bounds__(256, 3)
void attn_kernel()
{
    __shared__ float sq[56][32];
    __shared__ float sk[56][32];
    __shared__ float sv[56][32];
    __shared__ float S[56][56];

    const int tid = threadIdx.x;
    const int bh  = blockIdx.x;
    const int b   = bh >> 3;
    const int h   = bh & 7;
    const int base = bh * (TOK * HDIM);

    for (int i = tid; i < 56 * 8; i += 256) {
        const int r = i >> 3;
        const int c = (i & 7) * 4;
        float4 vq, vk, vv;
        if (r < TOK) {
            vq = ld4(g_q + base + r * HDIM + c);
            vk = ld4(g_k + base + r * HDIM + c);
            vv = ld4(g_v + base + r * HDIM + c);
        } else {
            vq = make_float4(0.f, 0.f, 0.f, 0.f);
            vk = vq; vv = vq;
        }
        st4(&sq[r][c], vq);
        st4(&sk[r][c], vk);
        st4(&sv[r][c], vv);
    }
    __syncthreads();

    // S = q k^T : 14x14 thread grid, 4x4 per thread
    if (tid < 196) {
        const int ty = tid / 14, tx = tid - ty * 14;
        const int i0 = ty * 4, j0 = tx * 4;
        float acc[4][4];
#pragma unroll
        for (int i = 0; i < 4; i++)
#pragma unroll
            for (int j = 0; j < 4; j++) acc[i][j] = 0.f;
#pragma unroll
        for (int d4 = 0; d4 < 8; d4++) {
            float4 qa[4], kb[4];
#pragma unroll
            for (int ii = 0; ii < 4; ii++) qa[ii] = ld4(&sq[i0 + ii][d4 * 4]);
#pragma unroll
            for (int jj = 0; jj < 4; jj++) kb[jj] = ld4(&sk[j0 + jj][d4 * 4]);
#pragma unroll
            for (int ii = 0; ii < 4; ii++)
#pragma unroll
                for (int jj = 0; jj < 4; jj++) {
                    acc[ii][jj] = fmaf(qa[ii].x, kb[jj].x, acc[ii][jj]);
                    acc[ii][jj] = fmaf(qa[ii].y, kb[jj].y, acc[ii][jj]);
                    acc[ii][jj] = fmaf(qa[ii].z, kb[jj].z, acc[ii][jj]);
                    acc[ii][jj] = fmaf(qa[ii].w, kb[jj].w, acc[ii][jj]);
                }
        }
#pragma unroll
        for (int ii = 0; ii < 4; ii++)
            st4(&S[i0 + ii][j0], make_float4(acc[ii][0], acc[ii][1], acc[ii][2], acc[ii][3]));
    }
    __syncthreads();

    // fused bias+mask: coalesced linear read
    {
        const float* bm = g_bm + (size_t)(((b & (NMASK - 1)) << 3) + h) * BMSTRIDE;
        for (int e = tid; e < TOK * TOK; e += 256) {
            const int i = e / TOK;
            const int j = e - i * TOK;
            S[i][j] += bm[e];
        }
    }
    __syncthreads();

    // softmax: warp per row
    const int warp = tid >> 5, lane = tid & 31;
    for (int i = warp; i < TOK; i += 8) {
        float x0 = S[i][lane];
        float x1 = (lane + 32 < TOK) ? S[i][lane + 32] : -1e30f;
        float mx = fmaxf(x0, x1);
#pragma unroll
        for (int off = 16; off > 0; off >>= 1)
            mx = fmaxf(mx, __shfl_xor_sync(0xffffffffu, mx, off));
        float e0 = __expf(x0 - mx);
        float e1 = (lane + 32 < TOK) ? __expf(x1 - mx) : 0.f;
        float s = e0 + e1;
#pragma unroll
        for (int off = 16; off > 0; off >>= 1)
            s += __shfl_xor_sync(0xffffffffu, s, off);
        const float inv = 1.f / s;
        S[i][lane] = e0 * inv;
        if (lane + 32 < TOK) S[i][lane + 32] = e1 * inv;
    }
    __syncthreads();

    // O = P @ V : 14x8 thread grid, 4x4 per thread
    if (tid < 112) {
        const int ty = tid >> 3, tx = tid & 7;
        const int i0 = ty * 4, d0 = tx * 4;
        float acc[4][4];
#pragma unroll
        for (int i = 0; i < 4; i++)
#pragma unroll
            for (int j = 0; j < 4; j++) acc[i][j] = 0.f;
        for (int j = 0; j < TOK; j++) {
            const float4 vv = ld4(&sv[j][d0]);
#pragma unroll
            for (int ii = 0; ii < 4; ii++) {
                const float p = S[i0 + ii][j];
                acc[ii][0] = fmaf(p, vv.x, acc[ii][0]);
                acc[ii][1] = fmaf(p, vv.y, acc[ii][1]);
                acc[ii][2] = fmaf(p, vv.z, acc[ii][2]);
                acc[ii][3] = fmaf(p, vv.w, acc[ii][3]);
            }
        }
#pragma unroll
        for (int ii = 0; ii < 4; ii++) {
            const int i = i0 + ii;
            if (i < TOK)
                st4(&g_att[(size_t)(b * TOK + i) * KDIM + h * HDIM + d0],
                    make_float4(acc[ii][0], acc[ii][1], acc[ii][2], acc[ii][3]));
        }
    }
}

// ---------------------------------------------------------------------------
extern "C" void kernel_launch(void* const* d_in, const int* in_sizes, int n_in,
                              void* d_out, int out_size)
{
    const float* x          = (const float*)d_in[0];
    const float* mask       = (const float*)d_in[1];
    const float* qkv_w      = (const float*)d_in[2];
    const float* qkv_b      = (const float*)d_in[3];
    const float* proj_w     = (const float*)d_in[4];
    const float* proj_b     = (const float*)d_in[5];
    const float* bias_table = (const float*)d_in[6];
    const int*   rel_index  = (const int*)d_in[7];
    float*       out        = (float*)d_out;

    // 0) fused bias+mask table (independent of GEMM)
    bm_precompute<<<NMASK * NH, 256>>>(bias_table, rel_index, mask);

    // 1) QKV tf32 GEMM + scatter to [b,h,t,d] (q pre-scaled)
    dim3 g1(MTOT / 128, 768 / 128);
    gemm_tf32<0><<<g1, 256>>>(x, qkv_w, qkv_b, nullptr, 768);

    // 2) attention per (window, head)
    attn_kernel<<<NWIN * NH, 256>>>();

    // 3) proj tf32 GEMM -> out
    dim3 g2(MTOT / 128, KDIM / 128);
    gemm_tf32<1><<<g2, 256>>>(nullptr, proj_w, proj_b, out, KDIM);
}

// round 4
// speedup vs baseline: 2.0219x; 1.4446x over previous
#include <cuda_runtime.h>
#include <cuda_bf16.h>
#include <cstdint>

#define TOK 49
#define HDIM 32
#define NH 8
#define NWIN 4096
#define MTOT (NWIN * TOK)   /* 200704 */
#define KDIM 256
#define NMASK 64
#define BMSTRIDE 2404

// ---------------- scratch (device globals: allocation-free) ----------------
__device__ float g_q[NWIN * NH * TOK * HDIM];   // [b,h,t,d]
__device__ float g_k[NWIN * NH * TOK * HDIM];
__device__ float g_v[NWIN * NH * TOK * HDIM];
__device__ float g_att[MTOT * KDIM];            // [b*49+t, h*32+d]
__device__ float g_bm[NMASK * NH * BMSTRIDE];   // fused bias+mask per (w,h)

__device__ __forceinline__ float4 ld4(const float* p) {
    return *reinterpret_cast<const float4*>(p);
}
__device__ __forceinline__ void st4(float* p, float4 v) {
    *reinterpret_cast<float4*>(p) = v;
}
__device__ __forceinline__ void st2(float* p, float2 v) {
    *reinterpret_cast<float2*>(p) = v;
}
__device__ __forceinline__ uint32_t f2tf(float f) {
    uint32_t u;
    asm("cvt.rna.tf32.f32 %0, %1;" : "=r"(u) : "f"(f));
    return u;
}
__device__ __forceinline__ void mma_tf32(float c[4],
                                         uint32_t a0, uint32_t a1, uint32_t a2, uint32_t a3,
                                         uint32_t b0, uint32_t b1) {
    asm volatile(
        "mma.sync.aligned.m16n8k8.row.col.f32.tf32.tf32.f32 "
        "{%0,%1,%2,%3}, {%4,%5,%6,%7}, {%8,%9}, {%0,%1,%2,%3};"
        : "+f"(c[0]), "+f"(c[1]), "+f"(c[2]), "+f"(c[3])
        : "r"(a0), "r"(a1), "r"(a2), "r"(a3), "r"(b0), "r"(b1));
}

// ---------------------------------------------------------------------------
// tf32 tensor-core GEMM (NT): C[m,n] = sum_k A[m,k]*B[n,k] + bias[n]
// (unchanged from round 3 — known correct)
// ---------------------------------------------------------------------------
#define SMS 140

template <int MODE>
__global__ __launch_bounds__(256, 2)
void gemm_tf32(const float* __restrict__ Ain, const float* __restrict__ B,
               const float* __restrict__ bias, float* __restrict__ C, int N)
{
    const int K = KDIM;
    const float* A = (MODE == 1) ? (const float*)g_att : Ain;

    __shared__ uint32_t As[16 * SMS];
    __shared__ uint32_t Bs[16 * SMS];

    const int tid  = threadIdx.x;
    const int m0   = blockIdx.x * 128;
    const int n0   = blockIdx.y * 128;
    const int warp = tid >> 5;
    const int lane = tid & 31;
    const int g    = lane >> 2;
    const int tig  = lane & 3;
    const int wm   = warp & 1;
    const int wn   = warp >> 1;
    const int mbase = wm * 64;
    const int nbase = wn * 32;

    const int r0  = tid >> 1;
    const int kc0 = (tid & 1) * 8;

    const float* Ap = A + (size_t)(m0 + r0) * K + kc0;
    const float* Bp = B + (size_t)(n0 + r0) * K + kc0;

    float acc[4][4][4];
#pragma unroll
    for (int mi = 0; mi < 4; mi++)
#pragma unroll
        for (int ni = 0; ni < 4; ni++)
#pragma unroll
            for (int e = 0; e < 4; e++) acc[mi][ni][e] = 0.f;

    float4 pa0 = ld4(Ap), pa1 = ld4(Ap + 4);
    float4 pb0 = ld4(Bp), pb1 = ld4(Bp + 4);

    for (int kt = 0; kt < K; kt += 16) {
        __syncthreads();
        As[(kc0 + 0) * SMS + r0] = f2tf(pa0.x);
        As[(kc0 + 1) * SMS + r0] = f2tf(pa0.y);
        As[(kc0 + 2) * SMS + r0] = f2tf(pa0.z);
        As[(kc0 + 3) * SMS + r0] = f2tf(pa0.w);
        As[(kc0 + 4) * SMS + r0] = f2tf(pa1.x);
        As[(kc0 + 5) * SMS + r0] = f2tf(pa1.y);
        As[(kc0 + 6) * SMS + r0] = f2tf(pa1.z);
        As[(kc0 + 7) * SMS + r0] = f2tf(pa1.w);
        Bs[(kc0 + 0) * SMS + r0] = f2tf(pb0.x);
        Bs[(kc0 + 1) * SMS + r0] = f2tf(pb0.y);
        Bs[(kc0 + 2) * SMS + r0] = f2tf(pb0.z);
        Bs[(kc0 + 3) * SMS + r0] = f2tf(pb0.w);
        Bs[(kc0 + 4) * SMS + r0] = f2tf(pb1.x);
        Bs[(kc0 + 5) * SMS + r0] = f2tf(pb1.y);
        Bs[(kc0 + 6) * SMS + r0] = f2tf(pb1.z);
        Bs[(kc0 + 7) * SMS + r0] = f2tf(pb1.w);
        __syncthreads();

        if (kt + 16 < K) {
            Ap += 16; Bp += 16;
            pa0 = ld4(Ap); pa1 = ld4(Ap + 4);
            pb0 = ld4(Bp); pb1 = ld4(Bp + 4);
        }

#pragma unroll
        for (int k8 = 0; k8 < 16; k8 += 8) {
            const int kr0 = (k8 + tig) * SMS;
            const int kr1 = (k8 + tig + 4) * SMS;
            uint32_t a[4][4], b[4][2];
#pragma unroll
            for (int mi = 0; mi < 4; mi++) {
                const int mg = mbase + mi * 16 + g;
                a[mi][0] = As[kr0 + mg];
                a[mi][1] = As[kr0 + mg + 8];
                a[mi][2] = As[kr1 + mg];
                a[mi][3] = As[kr1 + mg + 8];
            }
#pragma unroll
            for (int ni = 0; ni < 4; ni++) {
                const int ng = nbase + ni * 8 + g;
                b[ni][0] = Bs[kr0 + ng];
                b[ni][1] = Bs[kr1 + ng];
            }
#pragma unroll
            for (int mi = 0; mi < 4; mi++)
#pragma unroll
                for (int ni = 0; ni < 4; ni++)
                    mma_tf32(acc[mi][ni], a[mi][0], a[mi][1], a[mi][2], a[mi][3],
                             b[ni][0], b[ni][1]);
        }
    }

    if (MODE == 0) {
        const float SC = 0.17677669529663687f;
#pragma unroll
        for (int mi = 0; mi < 4; mi++) {
#pragma unroll
            for (int half = 0; half < 2; half++) {
                const int m  = m0 + mbase + mi * 16 + g + half * 8;
                const int bw = m / TOK;
                const int t  = m - bw * TOK;
#pragma unroll
                for (int ni = 0; ni < 4; ni++) {
                    const int n     = n0 + nbase + ni * 8 + 2 * tig;
                    const int which = n >> 8;
                    const int h     = (n >> 5) & 7;
                    const int d     = n & 31;
                    float2 v;
                    v.x = acc[mi][ni][half * 2 + 0] + bias[n + 0];
                    v.y = acc[mi][ni][half * 2 + 1] + bias[n + 1];
                    if (which == 0) { v.x *= SC; v.y *= SC; }
                    float* dst = (which == 0) ? g_q : (which == 1) ? g_k : g_v;
                    st2(&dst[(size_t)((bw * NH + h) * TOK + t) * HDIM + d], v);
                }
            }
        }
    } else {
#pragma unroll
        for (int mi = 0; mi < 4; mi++) {
#pragma unroll
            for (int half = 0; half < 2; half++) {
                const int m = m0 + mbase + mi * 16 + g + half * 8;
#pragma unroll
                for (int ni = 0; ni < 4; ni++) {
                    const int n = n0 + nbase + ni * 8 + 2 * tig;
                    float2 v;
                    v.x = acc[mi][ni][half * 2 + 0] + bias[n + 0];
                    v.y = acc[mi][ni][half * 2 + 1] + bias[n + 1];
                    st2(C + (size_t)m * N + n, v);
                }
            }
        }
    }
}

// ---------------------------------------------------------------------------
// Precompute fused bias+mask
// ---------------------------------------------------------------------------
__global__ void bm_precompute(const float* __restrict__ bias_table,
                              const int* __restrict__ rel_index,
                              const float* __restrict__ mask)
{
    const int w = blockIdx.x >> 3;
    float* dst = g_bm + (size_t)blockIdx.x * BMSTRIDE;
    const int h = blockIdx.x & 7;
    const float* mrow = mask + (size_t)w * (TOK * TOK);
    for (int e = threadIdx.x; e < TOK * TOK; e += 256)
        dst[e] = bias_table[rel_index[e] * NH + h] + mrow[e];
}

// ---------------------------------------------------------------------------
// Warp-synchronous attention: one block per (b,h), 8 warps x 7 rows each
// (overlapping rows -> benign identical-value races). One __syncthreads total.
// ---------------------------------------------------------------------------
#define QS 36   // q/k/v smem row stride (floats): 144B, 16B-aligned, conflict-free
#define PS 56   // p smem row stride

__global__ __launch_bounds__(256)
void attn_kernel()
{
    __shared__ float sq[TOK * QS];
    __shared__ float sk[TOK * QS];
    __shared__ float sv[56 * QS];        // rows 49..55 zero-padded
    __shared__ float sp[TOK * PS];       // cols 49..55 zero-padded

    const int tid  = threadIdx.x;
    const int warp = tid >> 5;
    const int lane = tid & 31;
    const int bh   = blockIdx.x;
    const int b    = bh >> 3;
    const int h    = bh & 7;
    const int base = bh * (TOK * HDIM);

    // load q,k,v into smem (v rows 49..55 zeroed)
    for (int idx = tid; idx < 56 * 8; idx += 256) {
        const int r = idx >> 3;
        const int c = (idx & 7) * 4;
        if (r < TOK) {
            st4(&sq[r * QS + c], ld4(g_q + base + r * HDIM + c));
            st4(&sk[r * QS + c], ld4(g_k + base + r * HDIM + c));
            st4(&sv[r * QS + c], ld4(g_v + base + r * HDIM + c));
        } else {
            st4(&sv[r * QS + c], make_float4(0.f, 0.f, 0.f, 0.f));
        }
    }
    __syncthreads();

    const int r0 = (warp == 7) ? 42 : warp * 6;   // 7 rows per warp, overlapping

    // ---------------- S = q k^T : lane = column (lane, lane+32) -------------
    float acc0[7], acc1[7];
#pragma unroll
    for (int ii = 0; ii < 7; ii++) { acc0[ii] = 0.f; acc1[ii] = 0.f; }

    const bool hi = (lane < 17);   // col lane+32 valid (32..48)
    const int klo = lane * QS;
    const int khi = (hi ? (lane + 32) : lane) * QS;   // dummy row for invalid lanes

#pragma unroll
    for (int dc = 0; dc < 32; dc += 8) {
        float4 k0a = ld4(&sk[klo + dc]);
        float4 k0b = ld4(&sk[klo + dc + 4]);
        float4 k1a = ld4(&sk[khi + dc]);
        float4 k1b = ld4(&sk[khi + dc + 4]);
#pragma unroll
        for (int ii = 0; ii < 7; ii++) {
            const int i = r0 + ii;
            const float4 qa = ld4(&sq[i * QS + dc]);
            const float4 qb = ld4(&sq[i * QS + dc + 4]);
            float a0 = acc0[ii], a1 = acc1[ii];
            a0 = fmaf(qa.x, k0a.x, a0); a1 = fmaf(qa.x, k1a.x, a1);
            a0 = fmaf(qa.y, k0a.y, a0); a1 = fmaf(qa.y, k1a.y, a1);
            a0 = fmaf(qa.z, k0a.z, a0); a1 = fmaf(qa.z, k1a.z, a1);
            a0 = fmaf(qa.w, k0a.w, a0); a1 = fmaf(qa.w, k1a.w, a1);
            a0 = fmaf(qb.x, k0b.x, a0); a1 = fmaf(qb.x, k1b.x, a1);
            a0 = fmaf(qb.y, k0b.y, a0); a1 = fmaf(qb.y, k1b.y, a1);
            a0 = fmaf(qb.z, k0b.z, a0); a1 = fmaf(qb.z, k1b.z, a1);
            a0 = fmaf(qb.w, k0b.w, a0); a1 = fmaf(qb.w, k1b.w, a1);
            acc0[ii] = a0; acc1[ii] = a1;
        }
    }

    // ------------- bias+mask + softmax (warp-local, in registers) -----------
    const float* bm = g_bm + (size_t)(((b & (NMASK - 1)) << 3) + h) * BMSTRIDE;
#pragma unroll
    for (int ii = 0; ii < 7; ii++) {
        const int i = r0 + ii;
        float x0 = acc0[ii] + bm[i * TOK + lane];
        float x1 = hi ? (acc1[ii] + bm[i * TOK + 32 + lane]) : -1e30f;
        float mx = fmaxf(x0, x1);
#pragma unroll
        for (int off = 16; off > 0; off >>= 1)
            mx = fmaxf(mx, __shfl_xor_sync(0xffffffffu, mx, off));
        float e0 = __expf(x0 - mx);
        float e1 = hi ? __expf(x1 - mx) : 0.f;
        float s = e0 + e1;
#pragma unroll
        for (int off = 16; off > 0; off >>= 1)
            s += __shfl_xor_sync(0xffffffffu, s, off);
        const float inv = 1.f / s;
        sp[i * PS + lane] = e0 * inv;
        if (lane < 24)                       // cols 32..55 (49..55 zeroed)
            sp[i * PS + 32 + lane] = hi ? e1 * inv : 0.f;
    }
    __syncwarp();

    // ---------------- O = P @ V : lane = d ----------------------------------
    float o[7];
#pragma unroll
    for (int ii = 0; ii < 7; ii++) o[ii] = 0.f;

#pragma unroll
    for (int jc = 0; jc < 56; jc += 8) {
        float v8[8];
#pragma unroll
        for (int jj = 0; jj < 8; jj++) v8[jj] = sv[(jc + jj) * QS + lane];
#pragma unroll
        for (int ii = 0; ii < 7; ii++) {
            const int i = r0 + ii;
            const float4 p0 = ld4(&sp[i * PS + jc]);
            const float4 p1 = ld4(&sp[i * PS + jc + 4]);
            float a = o[ii];
            a = fmaf(p0.x, v8[0], a);
            a = fmaf(p0.y, v8[1], a);
            a = fmaf(p0.z, v8[2], a);
            a = fmaf(p0.w, v8[3], a);
            a = fmaf(p1.x, v8[4], a);
            a = fmaf(p1.y, v8[5], a);
            a = fmaf(p1.z, v8[6], a);
            a = fmaf(p1.w, v8[7], a);
            o[ii] = a;
        }
    }

#pragma unroll
    for (int ii = 0; ii < 7; ii++) {
        const int i = r0 + ii;
        g_att[(size_t)(b * TOK + i) * KDIM + h * HDIM + lane] = o[ii];
    }
}

// ---------------------------------------------------------------------------
extern "C" void kernel_launch(void* const* d_in, const int* in_sizes, int n_in,
                              void* d_out, int out_size)
{
    const float* x          = (const float*)d_in[0];
    const float* mask       = (const float*)d_in[1];
    const float* qkv_w      = (const float*)d_in[2];
    const float* qkv_b      = (const float*)d_in[3];
    const float* proj_w     = (const float*)d_in[4];
    const float* proj_b     = (const float*)d_in[5];
    const float* bias_table = (const float*)d_in[6];
    const int*   rel_index  = (const int*)d_in[7];
    float*       out        = (float*)d_out;

    bm_precompute<<<NMASK * NH, 256>>>(bias_table, rel_index, mask);

    dim3 g1(MTOT / 128, 768 / 128);
    gemm_tf32<0><<<g1, 256>>>(x, qkv_w, qkv_b, nullptr, 768);

    attn_kernel<<<NWIN * NH, 256>>>();

    dim3 g2(MTOT / 128, KDIM / 128);
    gemm_tf32<1><<<g2, 256>>>(nullptr, proj_w, proj_b, out, KDIM);
}